// round 4
// baseline (speedup 1.0000x reference)
#include <cuda_runtime.h>
#include <cuda_bf16.h>

// DET_PROB hierarchical cumprod expansion — coalesced remap.
// B0=8, B1=16, B2=16 -> 2048 leaves per row, 128 leaf-groups of 16.
//
// 4 lanes cooperate on one leaf group: each lane owns one float4 chunk.
// All dc2 loads / out stores are fully coalesced (32 lanes x 16B contiguous),
// halving L1tex wavefronts vs the 64B-per-thread layout.
// Cross-chunk cumprod dependency resolved via 4-lane segmented shfl scan.

#define B0 8
#define B1 16
#define B2 16

__global__ __launch_bounds__(256) void det_prob_kernel(
    const float* __restrict__ dc0,
    const float* __restrict__ dc1,
    const float* __restrict__ dc2,
    float* __restrict__ out,
    int n_chunks)   // BATCH * 128 * 4
{
    int t = blockIdx.x * blockDim.x + threadIdx.x;
    if (t >= n_chunks) return;   // grid is an exact multiple; guard never fires

    int G   = t >> 2;          // leaf group index
    int c   = t & 3;           // chunk within group (4 floats each)
    int row = G >> 7;          // batch row
    int g   = G & 127;         // group within row
    int a0  = g >> 4;
    int a1  = g & 15;

    // ---- c0 = cumprod(dc0[row])[a0] ---- (2x float4 broadcast L1 hits)
    const float4* r0 = (const float4*)(dc0 + (size_t)row * B0);
    float4 p0 = __ldg(&r0[0]);
    float4 p1 = __ldg(&r0[1]);
    float v0[8] = {p0.x, p0.y, p0.z, p0.w, p1.x, p1.y, p1.z, p1.w};
    float c0 = 1.0f;
#pragma unroll
    for (int k = 0; k < B0; k++)
        c0 *= (k <= a0) ? v0[k] : 1.0f;

    // ---- c1 = within-group cumprod of dc1[row, a0*16 ..][a1] ----
    const float4* r1 = (const float4*)(dc1 + (size_t)row * (B0 * B1) + a0 * B1);
    float4 q0 = __ldg(&r1[0]);
    float4 q1 = __ldg(&r1[1]);
    float4 q2 = __ldg(&r1[2]);
    float4 q3 = __ldg(&r1[3]);
    float v1[16] = {q0.x, q0.y, q0.z, q0.w, q1.x, q1.y, q1.z, q1.w,
                    q2.x, q2.y, q2.z, q2.w, q3.x, q3.y, q3.z, q3.w};
    float c1 = 1.0f;
#pragma unroll
    for (int k = 0; k < B1; k++)
        c1 *= (k <= a1) ? v1[k] : 1.0f;

    float pfx = c0 * c1;   // prefix carried into the leaf group

    // ---- leaf chunk: 4 contiguous dc2 values, fully coalesced ----
    size_t base = (size_t)t * 4;            // == G*16 + c*4
    float4 x = __ldg((const float4*)(dc2 + base));

    // local cumprod within chunk (left-to-right, matches reference order)
    float l0 = x.x;
    float l1 = l0 * x.y;
    float l2 = l1 * x.z;
    float l3 = l2 * x.w;

    // segmented inclusive scan of chunk totals over the 4-lane group
    const unsigned mask = 0xFFFFFFFFu;
    float s = l3;
    float u = __shfl_up_sync(mask, s, 1);
    if (c >= 1) s *= u;
    u = __shfl_up_sync(mask, s, 2);
    if (c >= 2) s *= u;
    // exclusive prefix of chunk totals for this lane
    float e = __shfl_up_sync(mask, s, 1);
    if (c == 0) e = 1.0f;

    float scale = pfx * e;
    float4 o;
    o.x = l0 * scale;
    o.y = l1 * scale;
    o.z = l2 * scale;
    o.w = l3 * scale;
    ((float4*)out)[t] = o;
}

extern "C" void kernel_launch(void* const* d_in, const int* in_sizes, int n_in,
                              void* d_out, int out_size) {
    const float* dc0 = (const float*)d_in[0];
    const float* dc1 = (const float*)d_in[1];
    const float* dc2 = (const float*)d_in[2];
    float* out = (float*)d_out;

    int n_chunks = out_size / 4;            // BATCH * 128 * 4
    int threads = 256;
    int blocks = (n_chunks + threads - 1) / threads;
    det_prob_kernel<<<blocks, threads>>>(dc0, dc1, dc2, out, n_chunks);
}

// round 5
// speedup vs baseline: 1.0972x; 1.0972x over previous
#include <cuda_runtime.h>
#include <cuda_bf16.h>

// DET_PROB hierarchical cumprod expansion — smem prefix + coalesced stream.
// B0=8, B1=16, B2=16 -> 2048 leaves/row, 128 leaf-groups of 16.
//
// One block = one batch row.
//  Phase 1: threads 0..127 compute prefix[g] = cumprod(dc0)[a0] *
//           within-group-cumprod(dc1)[a0][a1] into smem (once per row).
//  Phase 2: 256 threads stream the row's 512 float4 chunks (2 each),
//           fully coalesced; within-group-of-16 cumprod via a 4-lane
//           segmented shfl scan. Streaming loads/stores (.cs) since
//           dc2/out have zero reuse.

#define B0 8
#define B1 16
#define B2 16
#define GROUPS 128            // leaf groups per row
#define ROW_ELEMS 2048        // B0*B1*B2
#define ROW_CHUNKS 512        // ROW_ELEMS/4
#define BLOCK 256

__global__ __launch_bounds__(BLOCK) void det_prob_kernel(
    const float* __restrict__ dc0,
    const float* __restrict__ dc1,
    const float* __restrict__ dc2,
    float* __restrict__ out)
{
    __shared__ float pfx[GROUPS];

    int row = blockIdx.x;
    int tid = threadIdx.x;

    // ---------- Phase 1: per-row prefixes (threads 0..127) ----------
    if (tid < GROUPS) {
        int a0 = tid >> 4;
        int a1 = tid & 15;

        // c0 = cumprod(dc0[row])[a0] — 8 broadcast L1 hits
        const float4* r0 = (const float4*)(dc0 + (size_t)row * B0);
        float4 p0 = __ldg(&r0[0]);
        float4 p1 = __ldg(&r0[1]);
        float v0[8] = {p0.x, p0.y, p0.z, p0.w, p1.x, p1.y, p1.z, p1.w};
        float c0 = v0[0];
#pragma unroll
        for (int k = 1; k < B0; k++)
            c0 *= (k <= a0) ? v0[k] : 1.0f;

        // c1 = within-group cumprod of dc1[row, a0*16 .. +16][a1]
        const float4* r1 = (const float4*)(dc1 + (size_t)row * (B0 * B1) + a0 * B1);
        float4 q0 = __ldg(&r1[0]);
        float4 q1 = __ldg(&r1[1]);
        float4 q2 = __ldg(&r1[2]);
        float4 q3 = __ldg(&r1[3]);
        float v1[16] = {q0.x, q0.y, q0.z, q0.w, q1.x, q1.y, q1.z, q1.w,
                        q2.x, q2.y, q2.z, q2.w, q3.x, q3.y, q3.z, q3.w};
        float c1 = v1[0];
#pragma unroll
        for (int k = 1; k < B1; k++)
            c1 *= (k <= a1) ? v1[k] : 1.0f;

        pfx[tid] = c0 * c1;
    }
    __syncthreads();

    // ---------- Phase 2: stream 512 chunks, 2 per thread ----------
    size_t row_base = (size_t)row * ROW_CHUNKS;   // in float4 units
    const float4* src = (const float4*)dc2;
    float4*       dst = (float4*)out;
    const unsigned mask = 0xFFFFFFFFu;
    int c = tid & 3;   // chunk-within-group == lane%4 for both iterations

#pragma unroll
    for (int it = 0; it < 2; it++) {
        int chunk = tid + it * BLOCK;             // 0..511
        int G = chunk >> 2;                       // leaf group in row

        float4 x = __ldcs(&src[row_base + chunk]);

        // local cumprod within the 4-float chunk (reference order)
        float l0 = x.x;
        float l1 = l0 * x.y;
        float l2 = l1 * x.z;
        float l3 = l2 * x.w;

        // segmented inclusive scan of chunk totals across the 4-lane group
        float s = l3;
        float u = __shfl_up_sync(mask, s, 1);
        if (c >= 1) s *= u;
        u = __shfl_up_sync(mask, s, 2);
        if (c >= 2) s *= u;
        float e = __shfl_up_sync(mask, s, 1);     // exclusive prefix
        if (c == 0) e = 1.0f;

        float scale = pfx[G] * e;
        float4 o;
        o.x = l0 * scale;
        o.y = l1 * scale;
        o.z = l2 * scale;
        o.w = l3 * scale;
        __stcs(&dst[row_base + chunk], o);
    }
}

extern "C" void kernel_launch(void* const* d_in, const int* in_sizes, int n_in,
                              void* d_out, int out_size) {
    const float* dc0 = (const float*)d_in[0];
    const float* dc1 = (const float*)d_in[1];
    const float* dc2 = (const float*)d_in[2];
    float* out = (float*)d_out;

    int batch = out_size / ROW_ELEMS;   // 32768 rows
    det_prob_kernel<<<batch, BLOCK>>>(dc0, dc1, dc2, out);
}

// round 6
// speedup vs baseline: 1.1449x; 1.0436x over previous
#include <cuda_runtime.h>
#include <cuda_bf16.h>

// DET_PROB hierarchical cumprod expansion — v4:
//   2 rows/block, 4 chunks/thread, streaming loads hoisted above the barrier.
// B0=8, B1=16, B2=16 -> 2048 leaves/row, 128 leaf-groups of 16.
//
// Phase 0: each thread front-batches its 4 dc2 float4 loads (MLP=4, .cs).
// Phase 1: 256 threads compute 256 prefixes (2 rows x 128 groups) -> smem,
//          latency overlapped with the in-flight streaming loads.
// Phase 2: 4-lane segmented shfl scan per chunk, scale by prefix, store (.cs).

#define B0 8
#define B1 16
#define B2 16
#define GROUPS 128            // leaf groups per row
#define ROW_ELEMS 2048        // B0*B1*B2
#define ROW_CHUNKS 512        // float4 chunks per row
#define ROWS_PER_BLK 2
#define BLK_CHUNKS (ROW_CHUNKS * ROWS_PER_BLK)   // 1024
#define BLOCK 256
#define CPT 4                 // chunks per thread

__global__ __launch_bounds__(BLOCK) void det_prob_kernel(
    const float* __restrict__ dc0,
    const float* __restrict__ dc1,
    const float* __restrict__ dc2,
    float* __restrict__ out)
{
    __shared__ float pfx[GROUPS * ROWS_PER_BLK];   // 256 prefixes

    int tid = threadIdx.x;
    size_t pair_base = (size_t)blockIdx.x * BLK_CHUNKS;   // float4 units

    // ---------- Phase 0: front-batch streaming loads ----------
    const float4* src = (const float4*)dc2;
    float4 x0 = __ldcs(&src[pair_base + tid + 0 * BLOCK]);
    float4 x1 = __ldcs(&src[pair_base + tid + 1 * BLOCK]);
    float4 x2 = __ldcs(&src[pair_base + tid + 2 * BLOCK]);
    float4 x3 = __ldcs(&src[pair_base + tid + 3 * BLOCK]);

    // ---------- Phase 1: one prefix per thread (overlaps loads) ----------
    {
        int r   = tid >> 7;               // row within pair (0/1)
        int g   = tid & 127;              // group within row
        int a0  = g >> 4;
        int a1  = g & 15;
        size_t row = (size_t)blockIdx.x * ROWS_PER_BLK + r;

        // c0 = cumprod(dc0[row])[a0]
        const float4* r0 = (const float4*)(dc0 + row * B0);
        float4 p0 = __ldg(&r0[0]);
        float4 p1 = __ldg(&r0[1]);
        float v0[8] = {p0.x, p0.y, p0.z, p0.w, p1.x, p1.y, p1.z, p1.w};
        float c0 = v0[0];
#pragma unroll
        for (int k = 1; k < B0; k++)
            c0 *= (k <= a0) ? v0[k] : 1.0f;

        // c1 = within-group cumprod of dc1[row, a0*16 .. +16][a1]
        const float4* r1 = (const float4*)(dc1 + row * (B0 * B1) + a0 * B1);
        float4 q0 = __ldg(&r1[0]);
        float4 q1 = __ldg(&r1[1]);
        float4 q2 = __ldg(&r1[2]);
        float4 q3 = __ldg(&r1[3]);
        float v1[16] = {q0.x, q0.y, q0.z, q0.w, q1.x, q1.y, q1.z, q1.w,
                        q2.x, q2.y, q2.z, q2.w, q3.x, q3.y, q3.z, q3.w};
        float c1 = v1[0];
#pragma unroll
        for (int k = 1; k < B1; k++)
            c1 *= (k <= a1) ? v1[k] : 1.0f;

        pfx[tid] = c0 * c1;
    }
    __syncthreads();

    // ---------- Phase 2: scan + scale + store ----------
    float4*       dst = (float4*)out;
    const unsigned mask = 0xFFFFFFFFu;
    int c = tid & 3;                      // chunk-within-group (all 4 iters)
    float4 xs[CPT] = {x0, x1, x2, x3};

#pragma unroll
    for (int it = 0; it < CPT; it++) {
        int chunk = tid + it * BLOCK;     // 0..1023 within the row pair
        int G = chunk >> 2;               // 0..255 -> pfx index

        float4 x = xs[it];
        float l0 = x.x;
        float l1 = l0 * x.y;
        float l2 = l1 * x.z;
        float l3 = l2 * x.w;

        // segmented inclusive scan of chunk totals across the 4-lane group
        float s = l3;
        float u = __shfl_up_sync(mask, s, 1);
        if (c >= 1) s *= u;
        u = __shfl_up_sync(mask, s, 2);
        if (c >= 2) s *= u;
        float e = __shfl_up_sync(mask, s, 1);   // exclusive prefix
        if (c == 0) e = 1.0f;

        float scale = pfx[G] * e;
        float4 o;
        o.x = l0 * scale;
        o.y = l1 * scale;
        o.z = l2 * scale;
        o.w = l3 * scale;
        __stcs(&dst[pair_base + chunk], o);
    }
}

extern "C" void kernel_launch(void* const* d_in, const int* in_sizes, int n_in,
                              void* d_out, int out_size) {
    const float* dc0 = (const float*)d_in[0];
    const float* dc1 = (const float*)d_in[1];
    const float* dc2 = (const float*)d_in[2];
    float* out = (float*)d_out;

    int batch = out_size / ROW_ELEMS;          // 32768 rows
    int blocks = batch / ROWS_PER_BLK;         // 16384 blocks
    det_prob_kernel<<<blocks, BLOCK>>>(dc0, dc1, dc2, out);
}